// round 7
// baseline (speedup 1.0000x reference)
#include <cuda_runtime.h>
#include <cuda_fp16.h>
#include <math.h>

#define NN 100000
#define EE 1600000
#define MM (EE + NN)
#define NB 49            // ceil(NN / 2048)
#define EPSV 1e-5f

// ---------------- scratch (static device allocations; no cudaMalloc) ----------------
__device__ int   g_is64 = 1;        // detection only ever clears -> stable across replays
__device__ int   g_deg[NN];
__device__ float g_dinv[NN];
__device__ int   g_start[NN];
__device__ int   g_cursor[NN];
__device__ int   g_tilesum[NB];
__device__ int   g_tileoff[NB];
__device__ int2  g_cw[MM];          // (src, norm-bits) per CSR slot
__device__ float g_s[NN];           // row sums of normalized adjacency
__device__ __align__(16) float g_h[NN * 64];      // GEMM out: fp16 (L1/2) or fp32 (L3)
__device__ __align__(16) float g_agg[NN * 64];    // aggregation output (fp32)
__device__ float g_stats1[128];     // [sum(64), sumsq(64)]
__device__ float g_stats2[128];
__device__ float g_W2f[64 * 64];    // BN1-folded W2
__device__ float g_W3f[64 * 40];    // BN2-folded W3
__device__ float g_t2[64];
__device__ float g_t3[64];
__device__ __align__(16) float g_zero64[64];

// ---------------- graph init + sampled dtype detect ----------------
__global__ void k_init(const long long* __restrict__ p) {
    int i = blockIdx.x * blockDim.x + threadIdx.x;
    if (i < NN) { g_deg[i] = 1; g_s[i] = 0.f; }      // self-loop
    if (i < 128) { g_stats1[i] = 0.f; g_stats2[i] = 0.f; }
    if (i < 64) g_zero64[i] = 0.f;
    if (i < 65536) {
        long long v = p[(size_t)i * 24];             // max idx < EE int64 slots
        if (v < 0 || v >= NN) g_is64 = 0;            // only writes 0: race-free
    }
}

__device__ __forceinline__ long long edge_at(const void* ei, int idx) {
    if (g_is64) return ((const long long*)ei)[idx];
    return (long long)((const int*)ei)[idx];
}

__global__ void k_degree(const void* __restrict__ ei) {
    int i = blockIdx.x * blockDim.x + threadIdx.x;
    if (i >= EE) return;
    long long d = edge_at(ei, EE + i);
    if ((unsigned long long)d < (unsigned long long)NN)
        atomicAdd(&g_deg[(int)d], 1);
}

__global__ void k_scanA() {   // block-tile sums (tile = 2048) + fused dinv
    int base = blockIdx.x * 2048;
    int s = 0;
    for (int i = threadIdx.x; i < 2048; i += 256) {
        int idx = base + i;
        if (idx < NN) {
            int d = g_deg[idx];
            s += d;
            g_dinv[idx] = rsqrtf((float)d);
        }
    }
    __shared__ int sh[256];
    sh[threadIdx.x] = s;
    __syncthreads();
    for (int o = 128; o > 0; o >>= 1) {
        if (threadIdx.x < o) sh[threadIdx.x] += sh[threadIdx.x + o];
        __syncthreads();
    }
    if (threadIdx.x == 0) g_tilesum[blockIdx.x] = sh[0];
}

__global__ void k_scanB() {   // exclusive scan of NB tile sums — warp-parallel
    int l = threadIdx.x;      // 32 threads
    int a = (l < NB) ? g_tilesum[l] : 0;
    int b = (l + 32 < NB) ? g_tilesum[l + 32] : 0;
    int A = a;
    #pragma unroll
    for (int o = 1; o < 32; o <<= 1) {
        int v = __shfl_up_sync(0xffffffffu, A, o);
        if (l >= o) A += v;
    }
    int tot = __shfl_sync(0xffffffffu, A, 31);
    int B = b;
    #pragma unroll
    for (int o = 1; o < 32; o <<= 1) {
        int v = __shfl_up_sync(0xffffffffu, B, o);
        if (l >= o) B += v;
    }
    if (l < NB) g_tileoff[l] = A - a;
    if (l + 32 < NB) g_tileoff[l + 32] = tot + B - b;
}

__global__ void k_scanC() {   // intra-tile exclusive scan -> start/cursor
    int tid = threadIdx.x;
    int base = blockIdx.x * 2048 + tid * 8;
    int loc[8];
    int s = 0;
    #pragma unroll
    for (int j = 0; j < 8; j++) {
        int idx = base + j;
        int d = (idx < NN) ? g_deg[idx] : 0;
        loc[j] = s; s += d;
    }
    __shared__ int sh[256];
    sh[tid] = s;
    __syncthreads();
    int run = s;
    for (int o = 1; o < 256; o <<= 1) {
        int v = (tid >= o) ? sh[tid - o] : 0;
        __syncthreads();
        sh[tid] += v;
        __syncthreads();
    }
    int off = g_tileoff[blockIdx.x] + sh[tid] - run;
    #pragma unroll
    for (int j = 0; j < 8; j++) {
        int idx = base + j;
        if (idx < NN) { int p = off + loc[j]; g_start[idx] = p; g_cursor[idx] = p; }
    }
}

// CSR fill + fused row-sum (s_d accumulated via float atomics).
__global__ void k_fill(const void* __restrict__ ei) {
    int i = blockIdx.x * blockDim.x + threadIdx.x;
    if (i >= MM) return;
    int s, d;
    if (i < EE) {
        long long ls = edge_at(ei, i);
        long long ld = edge_at(ei, EE + i);
        if ((unsigned long long)ls >= (unsigned long long)NN) return;
        if ((unsigned long long)ld >= (unsigned long long)NN) return;
        s = (int)ls; d = (int)ld;
    } else {
        s = i - EE; d = s;
    }
    float w = g_dinv[s] * g_dinv[d];
    int pos = atomicAdd(&g_cursor[d], 1);
    g_cw[pos] = make_int2(s, __float_as_int(w));
    atomicAdd(&g_s[d], w);
}

// ---------------- GEMM: out[N x NC] = in[N x 64] @ W[64 x NC] ----------------
// fp32 compute; output fp16 (HOUT, row stride 64 halves) or fp32.
// blockDim must be (NC/4)*16; block tile = 64 rows x NC cols.
template <int NC, bool HOUT>
__global__ void k_gemm(const float* __restrict__ in, const float* __restrict__ W,
                       void* __restrict__ out) {
    __shared__ float XsT[64 * 68];   // [k][row], padded
    __shared__ float Ws[64 * NC];    // [k][j]
    const int nth = (NC / 4) * 16;
    int tid = threadIdx.x;
    int row0 = blockIdx.x * 64;

    for (int i = tid; i < 64 * NC / 4; i += nth)
        ((float4*)Ws)[i] = ((const float4*)W)[i];

    for (int i = tid; i < 64 * 16; i += nth) {
        int r = i & 63, k4 = i >> 6;
        int gr = row0 + r;
        float4 v = make_float4(0.f, 0.f, 0.f, 0.f);
        if (gr < NN) v = ((const float4*)(in + (size_t)gr * 64))[k4];
        XsT[(k4 * 4 + 0) * 68 + r] = v.x;
        XsT[(k4 * 4 + 1) * 68 + r] = v.y;
        XsT[(k4 * 4 + 2) * 68 + r] = v.z;
        XsT[(k4 * 4 + 3) * 68 + r] = v.w;
    }
    __syncthreads();

    int tc = tid % (NC / 4), tr = tid / (NC / 4);
    int c0 = tc * 4, r0 = tr * 4;
    float acc[4][4];
    #pragma unroll
    for (int i = 0; i < 4; i++)
        #pragma unroll
        for (int j = 0; j < 4; j++) acc[i][j] = 0.f;

    #pragma unroll 8
    for (int k = 0; k < 64; k++) {
        float4 b = *(const float4*)&Ws[k * NC + c0];
        float4 a = *(const float4*)&XsT[k * 68 + r0];
        acc[0][0] += a.x * b.x; acc[0][1] += a.x * b.y; acc[0][2] += a.x * b.z; acc[0][3] += a.x * b.w;
        acc[1][0] += a.y * b.x; acc[1][1] += a.y * b.y; acc[1][2] += a.y * b.z; acc[1][3] += a.y * b.w;
        acc[2][0] += a.z * b.x; acc[2][1] += a.z * b.y; acc[2][2] += a.z * b.z; acc[2][3] += a.z * b.w;
        acc[3][0] += a.w * b.x; acc[3][1] += a.w * b.y; acc[3][2] += a.w * b.z; acc[3][3] += a.w * b.w;
    }

    #pragma unroll
    for (int i = 0; i < 4; i++) {
        int gr = row0 + r0 + i;
        if (gr < NN) {
            if (HOUT) {
                __half2 h0 = __floats2half2_rn(acc[i][0], acc[i][1]);
                __half2 h1 = __floats2half2_rn(acc[i][2], acc[i][3]);
                __half2* o2 = (__half2*)((__half*)out + (size_t)gr * 64 + c0);
                o2[0] = h0; o2[1] = h1;
            } else {
                *(float4*)&((float*)out)[(size_t)gr * NC + c0] =
                    make_float4(acc[i][0], acc[i][1], acc[i][2], acc[i][3]);
            }
        }
    }
}

// ---------------- aggregation (NC=64, fp16 h) + fused BN stats ----------------
// Quarter-warp per edge: fp16 row = 128B = 8 lanes x LDG.128; one warp LDG.128
// fetches 4 edges. 512 threads/block, grid 6250 -> exactly NN warps (no remainder,
// so __syncthreads is safe). Stats accumulated in shared, flushed once per block.
__global__ void __launch_bounds__(512)
k_agg64h(const uint4* __restrict__ h4, const float* __restrict__ bias,
         const float* __restrict__ t, float* __restrict__ out,
         float* __restrict__ st) {
    __shared__ float ssum[64], ssq[64];
    int tid = threadIdx.x;
    if (tid < 64) { ssum[tid] = 0.f; ssq[tid] = 0.f; }
    __syncthreads();

    int wid  = blockIdx.x * 16 + (tid >> 5);        // node id (always < NN)
    int lane = tid & 31;
    int q = lane >> 3, ql = lane & 7;
    int stt = g_start[wid], en = stt + g_deg[wid];
    float acc[8];
    #pragma unroll
    for (int i = 0; i < 8; i++) acc[i] = 0.f;

    #pragma unroll 2
    for (int e = stt + q; e < en; e += 4) {
        int2 c = __ldg(&g_cw[e]);
        uint4 v = __ldg(h4 + (size_t)c.x * 8 + ql);   // 8 halves of the row
        float w = __int_as_float(c.y);
        float2 f;
        f = __half22float2(*(const __half2*)&v.x); acc[0] += w * f.x; acc[1] += w * f.y;
        f = __half22float2(*(const __half2*)&v.y); acc[2] += w * f.x; acc[3] += w * f.y;
        f = __half22float2(*(const __half2*)&v.z); acc[4] += w * f.x; acc[5] += w * f.y;
        f = __half22float2(*(const __half2*)&v.w); acc[6] += w * f.x; acc[7] += w * f.y;
    }
    #pragma unroll
    for (int i = 0; i < 8; i++) {
        acc[i] += __shfl_xor_sync(0xffffffffu, acc[i], 8);
        acc[i] += __shfl_xor_sync(0xffffffffu, acc[i], 16);
    }
    if (q == 0) {   // lanes 0-7 hold full sums for cols ql*8 .. ql*8+7
        float sd = g_s[wid];
        const float4* b4 = (const float4*)(bias + ql * 8);
        const float4* t4 = (const float4*)(t + ql * 8);
        float4 b0 = __ldg(b4), b1 = __ldg(b4 + 1);
        float4 t0 = __ldg(t4), t1 = __ldg(t4 + 1);
        float o[8];
        o[0] = acc[0] + b0.x + sd * t0.x;
        o[1] = acc[1] + b0.y + sd * t0.y;
        o[2] = acc[2] + b0.z + sd * t0.z;
        o[3] = acc[3] + b0.w + sd * t0.w;
        o[4] = acc[4] + b1.x + sd * t1.x;
        o[5] = acc[5] + b1.y + sd * t1.y;
        o[6] = acc[6] + b1.z + sd * t1.z;
        o[7] = acc[7] + b1.w + sd * t1.w;
        float4* op = (float4*)(out + (size_t)wid * 64 + ql * 8);
        op[0] = make_float4(o[0], o[1], o[2], o[3]);
        op[1] = make_float4(o[4], o[5], o[6], o[7]);
        #pragma unroll
        for (int i = 0; i < 8; i++) {
            atomicAdd(&ssum[ql * 8 + i], o[i]);
            atomicAdd(&ssq[ql * 8 + i], o[i] * o[i]);
        }
    }
    __syncthreads();
    if (tid < 64) {
        atomicAdd(&st[tid], ssum[tid]);
        atomicAdd(&st[tid + 64], ssq[tid]);
    }
}

// ---------------- aggregation (NC=40, fp32 h) + fused log_softmax ----------------
__global__ void k_agg40lsm(const float* __restrict__ h, const float* __restrict__ bias,
                           const float* __restrict__ t, float* __restrict__ emb,
                           float* __restrict__ out) {
    int wid  = (blockIdx.x * blockDim.x + threadIdx.x) >> 5;
    int lane = threadIdx.x & 31;
    if (wid >= NN) return;
    bool act = lane < 20;
    int ln = act ? lane : 0;                 // keep loads in-bounds for idle lanes
    const float2* h2 = (const float2*)h;     // row stride = 20 float2
    int e = g_start[wid], en = e + g_deg[wid];
    float ax = 0.f, ay = 0.f;
    while (e + 4 <= en) {
        int2 c0 = __ldg(&g_cw[e]);
        int2 c1 = __ldg(&g_cw[e + 1]);
        int2 c2 = __ldg(&g_cw[e + 2]);
        int2 c3 = __ldg(&g_cw[e + 3]);
        float2 v0 = __ldg(h2 + (size_t)c0.x * 20 + ln);
        float2 v1 = __ldg(h2 + (size_t)c1.x * 20 + ln);
        float2 v2 = __ldg(h2 + (size_t)c2.x * 20 + ln);
        float2 v3 = __ldg(h2 + (size_t)c3.x * 20 + ln);
        float w0 = __int_as_float(c0.y), w1 = __int_as_float(c1.y);
        float w2 = __int_as_float(c2.y), w3 = __int_as_float(c3.y);
        ax += w0 * v0.x; ay += w0 * v0.y;
        ax += w1 * v1.x; ay += w1 * v1.y;
        ax += w2 * v2.x; ay += w2 * v2.y;
        ax += w3 * v3.x; ay += w3 * v3.y;
        e += 4;
    }
    while (e < en) {
        int2 c = __ldg(&g_cw[e++]);
        float2 v = __ldg(h2 + (size_t)c.x * 20 + ln);
        float w = __int_as_float(c.y);
        ax += w * v.x; ay += w * v.y;
    }
    float sd = g_s[wid];
    float v0 = 0.f, v1 = 0.f;
    if (act) {
        int c = lane * 2;
        v0 = ax + bias[c]     + sd * t[c];
        v1 = ay + bias[c + 1] + sd * t[c + 1];
        ((float2*)emb)[(size_t)wid * 20 + lane] = make_float2(v0, v1);
    }
    float m = act ? fmaxf(v0, v1) : -3.4e38f;
    #pragma unroll
    for (int o = 16; o > 0; o >>= 1) m = fmaxf(m, __shfl_xor_sync(0xffffffffu, m, o));
    float s = act ? (__expf(v0 - m) + __expf(v1 - m)) : 0.f;
    #pragma unroll
    for (int o = 16; o > 0; o >>= 1) s += __shfl_xor_sync(0xffffffffu, s, o);
    float lse = m + logf(s);
    if (act)
        ((float2*)out)[(size_t)wid * 20 + lane] = make_float2(v0 - lse, v1 - lse);
}

// ---------------- fold BN into next layer's weights ----------------
template <int NCN>
__global__ void k_fold(const float* __restrict__ W, const float* __restrict__ g,
                       const float* __restrict__ be, const float* __restrict__ st,
                       float* __restrict__ Wf, float* __restrict__ t) {
    __shared__ float a[64], c[64];
    int tid = threadIdx.x;
    if (tid < 64) {
        float mean = st[tid] * (1.f / NN);
        float var  = st[tid + 64] * (1.f / NN) - mean * mean;
        float ai = g[tid] * rsqrtf(var + EPSV);
        a[tid] = ai;
        c[tid] = be[tid] - mean * ai;
    }
    __syncthreads();
    for (int i = tid; i < 64 * NCN; i += 256) Wf[i] = a[i / NCN] * W[i];
    if (tid < NCN) {
        float tv = 0.f;
        #pragma unroll
        for (int k = 0; k < 64; k++) tv += c[k] * W[k * NCN + tid];
        t[tid] = tv;
    }
}

// ---------------- launcher ----------------
extern "C" void kernel_launch(void* const* d_in, const int* in_sizes, int n_in,
                              void* d_out, int out_size) {
    const float* x   = (const float*)d_in[0];
    const void*  ei  = d_in[1];                 // int32 or int64, detected on device
    const float* W1  = (const float*)d_in[2];
    const float* b1  = (const float*)d_in[3];
    const float* W2  = (const float*)d_in[4];
    const float* b2  = (const float*)d_in[5];
    const float* W3  = (const float*)d_in[6];
    const float* b3  = (const float*)d_in[7];
    const float* g1  = (const float*)d_in[8];
    const float* be1 = (const float*)d_in[9];
    const float* g2  = (const float*)d_in[10];
    const float* be2 = (const float*)d_in[11];
    float* out = (float*)d_out;

    float *hP, *aP, *W2fP, *W3fP, *t2P, *t3P, *z64P, *s1P, *s2P;
    cudaGetSymbolAddress((void**)&hP,   g_h);
    cudaGetSymbolAddress((void**)&aP,   g_agg);
    cudaGetSymbolAddress((void**)&W2fP, g_W2f);
    cudaGetSymbolAddress((void**)&W3fP, g_W3f);
    cudaGetSymbolAddress((void**)&t2P,  g_t2);
    cudaGetSymbolAddress((void**)&t3P,  g_t3);
    cudaGetSymbolAddress((void**)&z64P, g_zero64);
    cudaGetSymbolAddress((void**)&s1P,  g_stats1);
    cudaGetSymbolAddress((void**)&s2P,  g_stats2);

    // output layout: (out, emb) concatenated
    float* emb = (out_size >= 2 * NN * 40) ? (out + NN * 40) : aP;

    // side stream for GEMM1 (independent of the graph-build chain).
    // Created fresh per call (host-side only; capture-time cost is not timed).
    cudaStream_t s1;
    cudaStreamCreateWithFlags(&s1, cudaStreamNonBlocking);
    cudaEvent_t ev0, ev1;
    cudaEventCreateWithFlags(&ev0, cudaEventDisableTiming);
    cudaEventCreateWithFlags(&ev1, cudaEventDisableTiming);

    // fork: GEMM1 on s1, build chain on the default stream
    cudaEventRecord(ev0, 0);
    cudaStreamWaitEvent(s1, ev0, 0);
    k_gemm<64, true><<<(NN + 63) / 64, 256, 0, s1>>>(x, W1, hP);
    cudaEventRecord(ev1, s1);

    // graph build (default stream)
    k_init  <<<(NN + 255) / 256, 256>>>((const long long*)ei);
    k_degree<<<(EE + 255) / 256, 256>>>(ei);
    k_scanA <<<NB, 256>>>();
    k_scanB <<<1, 32>>>();
    k_scanC <<<NB, 256>>>();
    k_fill  <<<(MM + 255) / 256, 256>>>(ei);

    // join: agg1 needs both fill (stream order) and GEMM1 (event)
    cudaStreamWaitEvent(0, ev1, 0);

    // layer 1 (h fp16, stats fused)
    k_agg64h  <<<NN / 16, 512>>>((const uint4*)hP, b1, z64P, aP, s1P);
    k_fold<64><<<1, 256>>>(W2, g1, be1, s1P, W2fP, t2P);

    // layer 2 (BN1 folded into W2, h fp16, stats fused)
    k_gemm<64, true><<<(NN + 63) / 64, 256>>>(aP, W2fP, hP);
    k_agg64h  <<<NN / 16, 512>>>((const uint4*)hP, b2, t2P, aP, s2P);
    k_fold<40><<<1, 256>>>(W3, g2, be2, s2P, W3fP, t3P);

    // layer 3 (BN2 folded into W3, fp32) -> emb + fused log_softmax -> out
    k_gemm<40, false><<<(NN + 63) / 64, 160>>>(aP, W3fP, hP);
    k_agg40lsm<<<(NN + 7) / 8, 256>>>(hP, b3, t3P, emb, out);
}

// round 8
// speedup vs baseline: 1.0883x; 1.0883x over previous
#include <cuda_runtime.h>
#include <cuda_fp16.h>
#include <math.h>

#define NN 100000
#define EE 1600000
#define MM (EE + NN)
#define NB 49            // ceil(NN / 2048)
#define EPSV 1e-5f

// ---------------- scratch (static device allocations; no cudaMalloc) ----------------
__device__ int   g_is64 = 1;        // detection only ever clears -> stable across replays
__device__ int   g_deg[NN];
__device__ float g_dinv[NN];
__device__ int   g_start[NN];
__device__ int   g_cursor[NN];
__device__ int   g_tilesum[NB];
__device__ int2  g_cw[MM];          // (src, norm-bits) per CSR slot
__device__ float g_s[NN];           // row sums of normalized adjacency
__device__ __align__(16) float g_h[NN * 64];      // GEMM out: fp16 (L1/2) or fp32 (L3)
__device__ __align__(16) float g_agg[NN * 64];    // aggregation output (fp32)
__device__ float g_stats1[128];     // [sum(64), sumsq(64)]
__device__ float g_stats2[128];
__device__ float g_W2f[64 * 64];    // BN1-folded W2
__device__ float g_W3f[64 * 40];    // BN2-folded W3
__device__ float g_t2[64];
__device__ float g_t3[64];
__device__ __align__(16) float g_zero64[64];

// ---------------- graph init + sampled dtype detect ----------------
__global__ void k_init(const long long* __restrict__ p) {
    int i = blockIdx.x * blockDim.x + threadIdx.x;
    if (i < NN) { g_deg[i] = 1; g_s[i] = 0.f; }      // self-loop
    if (i < 128) { g_stats1[i] = 0.f; g_stats2[i] = 0.f; }
    if (i < 64) g_zero64[i] = 0.f;
    if (i < 65536) {
        long long v = p[(size_t)i * 24];             // max idx < EE int64 slots
        if (v < 0 || v >= NN) g_is64 = 0;            // only writes 0: race-free
    }
}

__device__ __forceinline__ long long edge_at(const void* ei, int idx) {
    if (g_is64) return ((const long long*)ei)[idx];
    return (long long)((const int*)ei)[idx];
}

__global__ void k_degree(const void* __restrict__ ei) {
    int i = blockIdx.x * blockDim.x + threadIdx.x;
    if (i >= EE) return;
    long long d = edge_at(ei, EE + i);
    if ((unsigned long long)d < (unsigned long long)NN)
        atomicAdd(&g_deg[(int)d], 1);
}

__global__ void k_scanA() {   // block-tile sums (tile = 2048) + fused dinv
    int base = blockIdx.x * 2048;
    int s = 0;
    for (int i = threadIdx.x; i < 2048; i += 256) {
        int idx = base + i;
        if (idx < NN) {
            int d = g_deg[idx];
            s += d;
            g_dinv[idx] = rsqrtf((float)d);
        }
    }
    __shared__ int sh[256];
    sh[threadIdx.x] = s;
    __syncthreads();
    for (int o = 128; o > 0; o >>= 1) {
        if (threadIdx.x < o) sh[threadIdx.x] += sh[threadIdx.x + o];
        __syncthreads();
    }
    if (threadIdx.x == 0) g_tilesum[blockIdx.x] = sh[0];
}

// intra-tile exclusive scan -> start/cursor; tile offset computed in-kernel
// (first warp sums g_tilesum[0..blockIdx), <=2 strided loads + warp reduce).
__global__ void k_scanC() {
    int tid = threadIdx.x;
    __shared__ int s_off;
    if (tid < 32) {
        int v = 0;
        for (int j = tid; j < blockIdx.x; j += 32) v += g_tilesum[j];
        #pragma unroll
        for (int o = 16; o > 0; o >>= 1) v += __shfl_xor_sync(0xffffffffu, v, o);
        if (tid == 0) s_off = v;
    }
    int base = blockIdx.x * 2048 + tid * 8;
    int loc[8];
    int s = 0;
    #pragma unroll
    for (int j = 0; j < 8; j++) {
        int idx = base + j;
        int d = (idx < NN) ? g_deg[idx] : 0;
        loc[j] = s; s += d;
    }
    __shared__ int sh[256];
    sh[tid] = s;
    __syncthreads();
    int run = s;
    for (int o = 1; o < 256; o <<= 1) {
        int v = (tid >= o) ? sh[tid - o] : 0;
        __syncthreads();
        sh[tid] += v;
        __syncthreads();
    }
    int off = s_off + sh[tid] - run;
    #pragma unroll
    for (int j = 0; j < 8; j++) {
        int idx = base + j;
        if (idx < NN) { int p = off + loc[j]; g_start[idx] = p; g_cursor[idx] = p; }
    }
}

// CSR fill + fused row-sum (s_d accumulated via float atomics).
__global__ void k_fill(const void* __restrict__ ei) {
    int i = blockIdx.x * blockDim.x + threadIdx.x;
    if (i >= MM) return;
    int s, d;
    if (i < EE) {
        long long ls = edge_at(ei, i);
        long long ld = edge_at(ei, EE + i);
        if ((unsigned long long)ls >= (unsigned long long)NN) return;
        if ((unsigned long long)ld >= (unsigned long long)NN) return;
        s = (int)ls; d = (int)ld;
    } else {
        s = i - EE; d = s;
    }
    float w = g_dinv[s] * g_dinv[d];
    int pos = atomicAdd(&g_cursor[d], 1);
    g_cw[pos] = make_int2(s, __float_as_int(w));
    atomicAdd(&g_s[d], w);
}

// ---------------- GEMM: out[N x NC] = in[N x 64] @ W[64 x NC] ----------------
// fp32 compute; output fp16 (HOUT, row stride 64 halves) or fp32.
// blockDim must be (NC/4)*16; block tile = 64 rows x NC cols.
template <int NC, bool HOUT>
__global__ void k_gemm(const float* __restrict__ in, const float* __restrict__ W,
                       void* __restrict__ out) {
    __shared__ float XsT[64 * 68];   // [k][row], padded
    __shared__ float Ws[64 * NC];    // [k][j]
    const int nth = (NC / 4) * 16;
    int tid = threadIdx.x;
    int row0 = blockIdx.x * 64;

    for (int i = tid; i < 64 * NC / 4; i += nth)
        ((float4*)Ws)[i] = ((const float4*)W)[i];

    for (int i = tid; i < 64 * 16; i += nth) {
        int r = i & 63, k4 = i >> 6;
        int gr = row0 + r;
        float4 v = make_float4(0.f, 0.f, 0.f, 0.f);
        if (gr < NN) v = ((const float4*)(in + (size_t)gr * 64))[k4];
        XsT[(k4 * 4 + 0) * 68 + r] = v.x;
        XsT[(k4 * 4 + 1) * 68 + r] = v.y;
        XsT[(k4 * 4 + 2) * 68 + r] = v.z;
        XsT[(k4 * 4 + 3) * 68 + r] = v.w;
    }
    __syncthreads();

    int tc = tid % (NC / 4), tr = tid / (NC / 4);
    int c0 = tc * 4, r0 = tr * 4;
    float acc[4][4];
    #pragma unroll
    for (int i = 0; i < 4; i++)
        #pragma unroll
        for (int j = 0; j < 4; j++) acc[i][j] = 0.f;

    #pragma unroll 8
    for (int k = 0; k < 64; k++) {
        float4 b = *(const float4*)&Ws[k * NC + c0];
        float4 a = *(const float4*)&XsT[k * 68 + r0];
        acc[0][0] += a.x * b.x; acc[0][1] += a.x * b.y; acc[0][2] += a.x * b.z; acc[0][3] += a.x * b.w;
        acc[1][0] += a.y * b.x; acc[1][1] += a.y * b.y; acc[1][2] += a.y * b.z; acc[1][3] += a.y * b.w;
        acc[2][0] += a.z * b.x; acc[2][1] += a.z * b.y; acc[2][2] += a.z * b.z; acc[2][3] += a.z * b.w;
        acc[3][0] += a.w * b.x; acc[3][1] += a.w * b.y; acc[3][2] += a.w * b.z; acc[3][3] += a.w * b.w;
    }

    #pragma unroll
    for (int i = 0; i < 4; i++) {
        int gr = row0 + r0 + i;
        if (gr < NN) {
            if (HOUT) {
                __half2 h0 = __floats2half2_rn(acc[i][0], acc[i][1]);
                __half2 h1 = __floats2half2_rn(acc[i][2], acc[i][3]);
                __half2* o2 = (__half2*)((__half*)out + (size_t)gr * 64 + c0);
                o2[0] = h0; o2[1] = h1;
            } else {
                *(float4*)&((float*)out)[(size_t)gr * NC + c0] =
                    make_float4(acc[i][0], acc[i][1], acc[i][2], acc[i][3]);
            }
        }
    }
}

// ---------------- aggregation (NC=64, fp16 h): quarter-warp uint4, 4 edges/iter ----------
// fp16 row = 128B = 8 lanes x LDG.128. Warp-quarter q handles edges st+q, st+q+4, ...
// One LDG.128 warp-instruction fetches 4 edges (4 lines). fp32 accumulate + output.
__global__ void k_agg64h(const uint4* __restrict__ h4, const float* __restrict__ bias,
                         const float* __restrict__ t, float* __restrict__ out) {
    int wid  = (blockIdx.x * blockDim.x + threadIdx.x) >> 5;
    int lane = threadIdx.x & 31;
    if (wid >= NN) return;
    int q = lane >> 3, ql = lane & 7;
    int st = g_start[wid], en = st + g_deg[wid];
    float acc[8];
    #pragma unroll
    for (int i = 0; i < 8; i++) acc[i] = 0.f;

    #pragma unroll 2
    for (int e = st + q; e < en; e += 4) {
        int2 c = __ldg(&g_cw[e]);
        uint4 v = __ldg(h4 + (size_t)c.x * 8 + ql);   // 8 halves of the row
        float w = __int_as_float(c.y);
        float2 f;
        f = __half22float2(*(const __half2*)&v.x); acc[0] += w * f.x; acc[1] += w * f.y;
        f = __half22float2(*(const __half2*)&v.y); acc[2] += w * f.x; acc[3] += w * f.y;
        f = __half22float2(*(const __half2*)&v.z); acc[4] += w * f.x; acc[5] += w * f.y;
        f = __half22float2(*(const __half2*)&v.w); acc[6] += w * f.x; acc[7] += w * f.y;
    }
    // combine the 4 quarters (same column group ql across quarters)
    #pragma unroll
    for (int i = 0; i < 8; i++) {
        acc[i] += __shfl_xor_sync(0xffffffffu, acc[i], 8);
        acc[i] += __shfl_xor_sync(0xffffffffu, acc[i], 16);
    }
    if (q == 0) {   // lanes 0-7 hold full sums for cols ql*8 .. ql*8+7
        float sd = g_s[wid];
        const float4* b4 = (const float4*)(bias + ql * 8);
        const float4* t4 = (const float4*)(t + ql * 8);
        float4 b0 = __ldg(b4), b1 = __ldg(b4 + 1);
        float4 t0 = __ldg(t4), t1 = __ldg(t4 + 1);
        float4 o0, o1;
        o0.x = acc[0] + b0.x + sd * t0.x;
        o0.y = acc[1] + b0.y + sd * t0.y;
        o0.z = acc[2] + b0.z + sd * t0.z;
        o0.w = acc[3] + b0.w + sd * t0.w;
        o1.x = acc[4] + b1.x + sd * t1.x;
        o1.y = acc[5] + b1.y + sd * t1.y;
        o1.z = acc[6] + b1.z + sd * t1.z;
        o1.w = acc[7] + b1.w + sd * t1.w;
        float4* op = (float4*)(out + (size_t)wid * 64 + ql * 8);
        op[0] = o0; op[1] = o1;
    }
}

// ---------------- aggregation (NC=40, fp32 h) + fused log_softmax ----------------
__global__ void k_agg40lsm(const float* __restrict__ h, const float* __restrict__ bias,
                           const float* __restrict__ t, float* __restrict__ emb,
                           float* __restrict__ out) {
    int wid  = (blockIdx.x * blockDim.x + threadIdx.x) >> 5;
    int lane = threadIdx.x & 31;
    if (wid >= NN) return;
    bool act = lane < 20;
    int ln = act ? lane : 0;                 // keep loads in-bounds for idle lanes
    const float2* h2 = (const float2*)h;     // row stride = 20 float2
    int e = g_start[wid], en = e + g_deg[wid];
    float ax = 0.f, ay = 0.f;
    while (e + 4 <= en) {
        int2 c0 = __ldg(&g_cw[e]);
        int2 c1 = __ldg(&g_cw[e + 1]);
        int2 c2 = __ldg(&g_cw[e + 2]);
        int2 c3 = __ldg(&g_cw[e + 3]);
        float2 v0 = __ldg(h2 + (size_t)c0.x * 20 + ln);
        float2 v1 = __ldg(h2 + (size_t)c1.x * 20 + ln);
        float2 v2 = __ldg(h2 + (size_t)c2.x * 20 + ln);
        float2 v3 = __ldg(h2 + (size_t)c3.x * 20 + ln);
        float w0 = __int_as_float(c0.y), w1 = __int_as_float(c1.y);
        float w2 = __int_as_float(c2.y), w3 = __int_as_float(c3.y);
        ax += w0 * v0.x; ay += w0 * v0.y;
        ax += w1 * v1.x; ay += w1 * v1.y;
        ax += w2 * v2.x; ay += w2 * v2.y;
        ax += w3 * v3.x; ay += w3 * v3.y;
        e += 4;
    }
    while (e < en) {
        int2 c = __ldg(&g_cw[e++]);
        float2 v = __ldg(h2 + (size_t)c.x * 20 + ln);
        float w = __int_as_float(c.y);
        ax += w * v.x; ay += w * v.y;
    }
    float sd = g_s[wid];
    float v0 = 0.f, v1 = 0.f;
    if (act) {
        int c = lane * 2;
        v0 = ax + bias[c]     + sd * t[c];
        v1 = ay + bias[c + 1] + sd * t[c + 1];
        ((float2*)emb)[(size_t)wid * 20 + lane] = make_float2(v0, v1);
    }
    float m = act ? fmaxf(v0, v1) : -3.4e38f;
    #pragma unroll
    for (int o = 16; o > 0; o >>= 1) m = fmaxf(m, __shfl_xor_sync(0xffffffffu, m, o));
    float s = act ? (__expf(v0 - m) + __expf(v1 - m)) : 0.f;
    #pragma unroll
    for (int o = 16; o > 0; o >>= 1) s += __shfl_xor_sync(0xffffffffu, s, o);
    float lse = m + logf(s);
    if (act)
        ((float2*)out)[(size_t)wid * 20 + lane] = make_float2(v0 - lse, v1 - lse);
}

// ---------------- BN column stats (sum, sumsq) ----------------
__global__ void k_stats(const float* __restrict__ a, float* __restrict__ st) {
    int col = threadIdx.x & 63, sub = threadIdx.x >> 6;
    float s = 0.f, q = 0.f;
    for (int r = blockIdx.x * 4 + sub; r < NN; r += gridDim.x * 4) {
        float v = a[(size_t)r * 64 + col];
        s += v; q += v * v;
    }
    __shared__ float shs[256], shq[256];
    shs[threadIdx.x] = s; shq[threadIdx.x] = q;
    __syncthreads();
    if (sub == 0) {
        s = shs[col] + shs[col + 64] + shs[col + 128] + shs[col + 192];
        q = shq[col] + shq[col + 64] + shq[col + 128] + shq[col + 192];
        atomicAdd(&st[col], s);
        atomicAdd(&st[col + 64], q);
    }
}

// ---------------- fold BN into next layer's weights ----------------
template <int NCN>
__global__ void k_fold(const float* __restrict__ W, const float* __restrict__ g,
                       const float* __restrict__ be, const float* __restrict__ st,
                       float* __restrict__ Wf, float* __restrict__ t) {
    __shared__ float a[64], c[64];
    int tid = threadIdx.x;
    if (tid < 64) {
        float mean = st[tid] * (1.f / NN);
        float var  = st[tid + 64] * (1.f / NN) - mean * mean;
        float ai = g[tid] * rsqrtf(var + EPSV);
        a[tid] = ai;
        c[tid] = be[tid] - mean * ai;
    }
    __syncthreads();
    for (int i = tid; i < 64 * NCN; i += 256) Wf[i] = a[i / NCN] * W[i];
    if (tid < NCN) {
        float tv = 0.f;
        #pragma unroll
        for (int k = 0; k < 64; k++) tv += c[k] * W[k * NCN + tid];
        t[tid] = tv;
    }
}

// ---------------- launcher ----------------
extern "C" void kernel_launch(void* const* d_in, const int* in_sizes, int n_in,
                              void* d_out, int out_size) {
    const float* x   = (const float*)d_in[0];
    const void*  ei  = d_in[1];                 // int32 or int64, detected on device
    const float* W1  = (const float*)d_in[2];
    const float* b1  = (const float*)d_in[3];
    const float* W2  = (const float*)d_in[4];
    const float* b2  = (const float*)d_in[5];
    const float* W3  = (const float*)d_in[6];
    const float* b3  = (const float*)d_in[7];
    const float* g1  = (const float*)d_in[8];
    const float* be1 = (const float*)d_in[9];
    const float* g2  = (const float*)d_in[10];
    const float* be2 = (const float*)d_in[11];
    float* out = (float*)d_out;

    float *hP, *aP, *W2fP, *W3fP, *t2P, *t3P, *z64P, *s1P, *s2P;
    cudaGetSymbolAddress((void**)&hP,   g_h);
    cudaGetSymbolAddress((void**)&aP,   g_agg);
    cudaGetSymbolAddress((void**)&W2fP, g_W2f);
    cudaGetSymbolAddress((void**)&W3fP, g_W3f);
    cudaGetSymbolAddress((void**)&t2P,  g_t2);
    cudaGetSymbolAddress((void**)&t3P,  g_t3);
    cudaGetSymbolAddress((void**)&z64P, g_zero64);
    cudaGetSymbolAddress((void**)&s1P,  g_stats1);
    cudaGetSymbolAddress((void**)&s2P,  g_stats2);

    // output layout: (out, emb) concatenated
    float* emb = (out_size >= 2 * NN * 40) ? (out + NN * 40) : aP;

    // graph build (single stream; R7 showed forked capture regresses)
    k_init  <<<(NN + 255) / 256, 256>>>((const long long*)ei);
    k_degree<<<(EE + 255) / 256, 256>>>(ei);
    k_scanA <<<NB, 256>>>();
    k_scanC <<<NB, 256>>>();
    k_fill  <<<(MM + 255) / 256, 256>>>(ei);

    // layer 1 (h in fp16)
    k_gemm<64, true><<<(NN + 63) / 64, 256>>>(x, W1, hP);
    k_agg64h  <<<(NN + 7) / 8, 256>>>((const uint4*)hP, b1, z64P, aP);
    k_stats   <<<256, 256>>>(aP, s1P);
    k_fold<64><<<1, 256>>>(W2, g1, be1, s1P, W2fP, t2P);

    // layer 2 (BN1 folded into W2, h in fp16)
    k_gemm<64, true><<<(NN + 63) / 64, 256>>>(aP, W2fP, hP);
    k_agg64h  <<<(NN + 7) / 8, 256>>>((const uint4*)hP, b2, t2P, aP);
    k_stats   <<<256, 256>>>(aP, s2P);
    k_fold<40><<<1, 256>>>(W3, g2, be2, s2P, W3fP, t3P);

    // layer 3 (BN2 folded into W3, fp32 throughout) -> emb + fused log_softmax -> out
    k_gemm<40, false><<<(NN + 63) / 64, 160>>>(aP, W3fP, hP);
    k_agg40lsm<<<(NN + 7) / 8, 256>>>(hP, b3, t3P, emb, out);
}